// round 1
// baseline (speedup 1.0000x reference)
#include <cuda_runtime.h>
#include <cuda_bf16.h>
#include <cstdint>

// ---------------------------------------------------------------------------
// QKVProjectedLinear: y_k = ((x @ A_all) @ C_k) @ A_k^T with C_k = B_k Ws_k^T B_k^T
// Folded: G_k = C_k @ A_k^T  [64,1024];  out_k = (x @ A_k) @ G_k
// ---------------------------------------------------------------------------

#define K3 3
#define DL 1024
#define DS 768
#define RK 64
#define NJ 192          // 3*64
#define NROWS 16384
#define DOUT 3072

// ------------------------- device scratch (no cudaMalloc allowed) ----------
__device__ float g_U[K3*RK*DS];          // B @ Ws^T          [3,64,768]
__device__ float g_Vp[K3*4*RK*RK];       // partial V         [3,4,64,64]
__device__ float g_V[K3*RK*RK];          // U @ B^T           [3,64,64]
__device__ float g_Gf[K3*RK*DL];         // V @ A^T           [3,64,1024]
__device__ __nv_bfloat16 g_Ah[DL*NJ];    // A_all hi  [1024,192]
__device__ __nv_bfloat16 g_Al[DL*NJ];    // A_all lo
__device__ __nv_bfloat16 g_Gh[K3*RK*DL]; // G hi  [3,64,1024]
__device__ __nv_bfloat16 g_Gl[K3*RK*DL]; // G lo

__device__ __forceinline__ void splitf(float v, __nv_bfloat16& h, __nv_bfloat16& l){
    h = __float2bfloat16(v);
    l = __float2bfloat16(v - __bfloat162float(h));
}

// ------------------------- phase 0: tiny fp32 GEMM chain -------------------
// U[k,r,s] = sum_t B[k,r,t] * W[(k*768+s), t]
__global__ void p0_U(const float* __restrict__ B, const float* __restrict__ W){
    int k = blockIdx.x, s0 = blockIdx.y*32;
    __shared__ float Bt[64][65];
    __shared__ float Wt[32][65];
    int tid = threadIdx.x;
    float acc[2][4] = {};
    int r0 = (tid & 31)*2, sq = (tid >> 5)*4;
    for (int t0 = 0; t0 < DS; t0 += 64){
        __syncthreads();
        #pragma unroll
        for (int i = 0; i < 16; i++){
            int idx = tid + (i<<8); int r = idx>>6, t = idx&63;
            Bt[r][t] = B[(k*64 + r)*DS + t0 + t];
        }
        #pragma unroll
        for (int i = 0; i < 8; i++){
            int idx = tid + (i<<8); int s = idx>>6, t = idx&63;
            Wt[s][t] = W[(size_t)(k*DS + s0 + s)*DS + t0 + t];
        }
        __syncthreads();
        #pragma unroll 8
        for (int t = 0; t < 64; t++){
            float a0 = Bt[r0][t], a1 = Bt[r0+1][t];
            #pragma unroll
            for (int j = 0; j < 4; j++){
                float b = Wt[sq+j][t];
                acc[0][j] += a0*b;
                acc[1][j] += a1*b;
            }
        }
    }
    #pragma unroll
    for (int i = 0; i < 2; i++)
        #pragma unroll
        for (int j = 0; j < 4; j++)
            g_U[(k*64 + r0 + i)*DS + s0 + sq + j] = acc[i][j];
}

// Vp[k,sc,r,q] = sum_{s in chunk sc} U[k,r,s] * B[k,q,s]
__global__ void p0_V(const float* __restrict__ B){
    int k = blockIdx.x, sc = blockIdx.y;
    __shared__ float Us[64][65];
    __shared__ float Bs[64][65];
    int tid = threadIdx.x;
    float acc[4][4] = {};
    int r0 = (tid & 15)*4, q0 = (tid >> 4)*4;
    for (int si = 0; si < 3; si++){
        int s0 = sc*192 + si*64;
        __syncthreads();
        #pragma unroll
        for (int i = 0; i < 16; i++){
            int idx = tid + (i<<8); int r = idx>>6, s = idx&63;
            Us[r][s] = g_U[(k*64 + r)*DS + s0 + s];
            Bs[r][s] = B[(k*64 + r)*DS + s0 + s];
        }
        __syncthreads();
        #pragma unroll 4
        for (int s = 0; s < 64; s++){
            float a[4], b[4];
            #pragma unroll
            for (int i = 0; i < 4; i++){ a[i] = Us[r0+i][s]; b[i] = Bs[q0+i][s]; }
            #pragma unroll
            for (int i = 0; i < 4; i++)
                #pragma unroll
                for (int j = 0; j < 4; j++) acc[i][j] += a[i]*b[j];
        }
    }
    #pragma unroll
    for (int i = 0; i < 4; i++)
        #pragma unroll
        for (int j = 0; j < 4; j++)
            g_Vp[((k*4 + sc)*64 + r0 + i)*64 + q0 + j] = acc[i][j];
}

__global__ void p0_Vred(){
    int idx = blockIdx.x*256 + threadIdx.x;
    if (idx < K3*RK*RK){
        int k = idx/(RK*RK), rq = idx%(RK*RK);
        float s = 0.f;
        #pragma unroll
        for (int sc = 0; sc < 4; sc++) s += g_Vp[(k*4 + sc)*RK*RK + rq];
        g_V[idx] = s;
    }
}

// G[k,r,e] = sum_q V[k,r,q] * A[k,e,q]
__global__ void p0_G(const float* __restrict__ A){
    int k = blockIdx.x, e0 = blockIdx.y*64;
    __shared__ float Vs[64][68];
    __shared__ float As[64][68];
    int tid = threadIdx.x;
    #pragma unroll
    for (int i = 0; i < 16; i++){
        int idx = tid + (i<<8); int a = idx>>6, b = idx&63;
        Vs[a][b] = g_V[k*RK*RK + a*64 + b];
        As[a][b] = A[(size_t)(k*DL + e0 + a)*RK + b];
    }
    __syncthreads();
    int r0 = (tid & 15)*4, ee = (tid >> 4)*4;
    float acc[4][4] = {};
    #pragma unroll 4
    for (int q = 0; q < 64; q++){
        float a[4], b[4];
        #pragma unroll
        for (int i = 0; i < 4; i++){ a[i] = Vs[r0+i][q]; b[i] = As[ee+i][q]; }
        #pragma unroll
        for (int i = 0; i < 4; i++)
            #pragma unroll
            for (int j = 0; j < 4; j++) acc[i][j] += a[i]*b[j];
    }
    #pragma unroll
    for (int i = 0; i < 4; i++)
        #pragma unroll
        for (int j = 0; j < 4; j++)
            g_Gf[(k*64 + r0 + i)*DL + e0 + ee + j] = acc[i][j];
}

// A[k,d,r] -> A_all[d, k*64+r] split hi/lo bf16
__global__ void p0_splitA(const float* __restrict__ A){
    int idx = blockIdx.x*256 + threadIdx.x;
    if (idx < K3*DL*RK){
        int k = idx/(DL*RK); int rem = idx%(DL*RK); int d = rem/RK; int r = rem%RK;
        __nv_bfloat16 h, l;
        splitf(A[idx], h, l);
        g_Ah[d*NJ + k*RK + r] = h;
        g_Al[d*NJ + k*RK + r] = l;
    }
}

__global__ void p0_splitG(){
    int idx = blockIdx.x*256 + threadIdx.x;
    if (idx < K3*RK*DL){
        __nv_bfloat16 h, l;
        splitf(g_Gf[idx], h, l);
        g_Gh[idx] = h;
        g_Gl[idx] = l;
    }
}

// ------------------------- main fused kernel -------------------------------
// smem layout (bytes):
#define XH_OFF   0          // [128][72] bf16 = 18432
#define XL_OFF   18432
#define AH_OFF   36864      // [64][200] bf16 = 25600
#define AL_OFF   62464      // end 88064
#define T1H_OFF  0          // [128][200] bf16 = 51200 (aliases stage-1 bufs)
#define T1L_OFF  51200      // end 102400
#define GH_OFF   102400     // [64][136] bf16 = 17408
#define GL_OFF   119808     // end 137216
#define SMEM_BYTES 137216
#define XPITCH 72
#define APITCH 200
#define TPITCH 200
#define GPITCH 136

__device__ __forceinline__ void ldsm4(uint32_t* r, const void* p){
    uint32_t a = (uint32_t)__cvta_generic_to_shared(p);
    asm volatile("ldmatrix.sync.aligned.m8n8.x4.shared.b16 {%0,%1,%2,%3}, [%4];"
        : "=r"(r[0]), "=r"(r[1]), "=r"(r[2]), "=r"(r[3]) : "r"(a));
}
__device__ __forceinline__ void ldsm4t(uint32_t* r, const void* p){
    uint32_t a = (uint32_t)__cvta_generic_to_shared(p);
    asm volatile("ldmatrix.sync.aligned.m8n8.x4.trans.shared.b16 {%0,%1,%2,%3}, [%4];"
        : "=r"(r[0]), "=r"(r[1]), "=r"(r[2]), "=r"(r[3]) : "r"(a));
}
__device__ __forceinline__ void mma_bf16(float* c, const uint32_t* a, const uint32_t* b){
    asm volatile("mma.sync.aligned.m16n8k16.row.col.f32.bf16.bf16.f32 "
        "{%0,%1,%2,%3}, {%4,%5,%6,%7}, {%8,%9}, {%0,%1,%2,%3};"
        : "+f"(c[0]), "+f"(c[1]), "+f"(c[2]), "+f"(c[3])
        : "r"(a[0]), "r"(a[1]), "r"(a[2]), "r"(a[3]), "r"(b[0]), "r"(b[1]));
}

__global__ __launch_bounds__(256, 1)
void qkv_main(const float* __restrict__ x, float* __restrict__ out){
    extern __shared__ char smem[];
    __nv_bfloat16* xh  = (__nv_bfloat16*)(smem + XH_OFF);
    __nv_bfloat16* xl  = (__nv_bfloat16*)(smem + XL_OFF);
    __nv_bfloat16* Ahs = (__nv_bfloat16*)(smem + AH_OFF);
    __nv_bfloat16* Als = (__nv_bfloat16*)(smem + AL_OFF);
    __nv_bfloat16* t1h = (__nv_bfloat16*)(smem + T1H_OFF);
    __nv_bfloat16* t1l = (__nv_bfloat16*)(smem + T1L_OFF);
    __nv_bfloat16* Ghs = (__nv_bfloat16*)(smem + GH_OFF);
    __nv_bfloat16* Gls = (__nv_bfloat16*)(smem + GL_OFF);

    int tid  = threadIdx.x;
    int warp = tid >> 5, lane = tid & 31;
    int wm = warp >> 1, wn = warp & 1;          // 4 (M) x 2 (N) warp grid
    int row0 = blockIdx.x * 128;

    int lrow = lane & 15;                        // ldmatrix row within tile
    int lcol = (lane >> 4) << 3;                 // ldmatrix col half select

    // ============== stage 1: t1[128,192] = x[128,1024] @ A_all =============
    float acc[2][12][4];
    #pragma unroll
    for (int i = 0; i < 2; i++)
        #pragma unroll
        for (int j = 0; j < 12; j++)
            #pragma unroll
            for (int q = 0; q < 4; q++) acc[i][j][q] = 0.f;

    for (int d0 = 0; d0 < DL; d0 += 64){
        // load+split x chunk [128][64]
        #pragma unroll
        for (int i = 0; i < 8; i++){
            int idx = tid + (i << 8);
            int r = idx >> 4, c4 = idx & 15;
            float4 v = *(const float4*)(x + (size_t)(row0 + r)*DL + d0 + (c4 << 2));
            __nv_bfloat16 h0,h1,h2,h3,l0,l1,l2,l3;
            splitf(v.x,h0,l0); splitf(v.y,h1,l1); splitf(v.z,h2,l2); splitf(v.w,h3,l3);
            __nv_bfloat162 t;
            __nv_bfloat162* ph = (__nv_bfloat162*)(xh + r*XPITCH + (c4 << 2));
            t.x=h0; t.y=h1; ph[0]=t;  t.x=h2; t.y=h3; ph[1]=t;
            __nv_bfloat162* pl = (__nv_bfloat162*)(xl + r*XPITCH + (c4 << 2));
            t.x=l0; t.y=l1; pl[0]=t;  t.x=l2; t.y=l3; pl[1]=t;
        }
        // load pre-split A chunk [64][192]
        #pragma unroll
        for (int i = 0; i < 6; i++){
            int idx = tid + (i << 8);
            int r = idx / 24, c = idx % 24;
            *(uint4*)(Ahs + r*APITCH + (c << 3)) = *(const uint4*)(g_Ah + (size_t)(d0 + r)*NJ + (c << 3));
            *(uint4*)(Als + r*APITCH + (c << 3)) = *(const uint4*)(g_Al + (size_t)(d0 + r)*NJ + (c << 3));
        }
        __syncthreads();
        #pragma unroll
        for (int ks = 0; ks < 4; ks++){
            uint32_t ah[2][4], al[2][4];
            #pragma unroll
            for (int mt = 0; mt < 2; mt++){
                int off = (wm*32 + mt*16 + lrow)*XPITCH + ks*16 + lcol;
                ldsm4(ah[mt], xh + off);
                ldsm4(al[mt], xl + off);
            }
            #pragma unroll
            for (int pp = 0; pp < 6; pp++){
                uint32_t bh[4], bl[4];
                int off = (ks*16 + lrow)*APITCH + wn*96 + pp*16 + lcol;
                ldsm4t(bh, Ahs + off);
                ldsm4t(bl, Als + off);
                #pragma unroll
                for (int mt = 0; mt < 2; mt++){
                    mma_bf16(acc[mt][2*pp],   ah[mt], bh);
                    mma_bf16(acc[mt][2*pp],   ah[mt], bl);
                    mma_bf16(acc[mt][2*pp],   al[mt], bh);
                    mma_bf16(acc[mt][2*pp+1], ah[mt], bh + 2);
                    mma_bf16(acc[mt][2*pp+1], ah[mt], bl + 2);
                    mma_bf16(acc[mt][2*pp+1], al[mt], bh + 2);
                }
            }
        }
        __syncthreads();
    }

    // spill t1 (split hi/lo) to smem
    #pragma unroll
    for (int mt = 0; mt < 2; mt++){
        int r0w = wm*32 + mt*16 + (lane >> 2);
        #pragma unroll
        for (int nt = 0; nt < 12; nt++){
            int c0 = wn*96 + nt*8 + ((lane & 3) << 1);
            __nv_bfloat16 h0,h1,l0,l1; __nv_bfloat162 t;
            splitf(acc[mt][nt][0], h0, l0); splitf(acc[mt][nt][1], h1, l1);
            t.x=h0; t.y=h1; *(__nv_bfloat162*)(t1h + r0w*TPITCH + c0) = t;
            t.x=l0; t.y=l1; *(__nv_bfloat162*)(t1l + r0w*TPITCH + c0) = t;
            splitf(acc[mt][nt][2], h0, l0); splitf(acc[mt][nt][3], h1, l1);
            t.x=h0; t.y=h1; *(__nv_bfloat162*)(t1h + (r0w+8)*TPITCH + c0) = t;
            t.x=l0; t.y=l1; *(__nv_bfloat162*)(t1l + (r0w+8)*TPITCH + c0) = t;
        }
    }

    // ============== stage 2: out chunks [128][128] = t1_k @ G_k chunk ======
    float acc2[2][8][4];
    for (int chunk = 0; chunk < 24; chunk++){
        int kq = chunk >> 3, e0 = (chunk & 7) << 7;
        #pragma unroll
        for (int i = 0; i < 4; i++){
            int idx = tid + (i << 8);
            int r = idx >> 4, c = idx & 15;
            *(uint4*)(Ghs + r*GPITCH + (c << 3)) = *(const uint4*)(g_Gh + (size_t)(kq*64 + r)*DL + e0 + (c << 3));
            *(uint4*)(Gls + r*GPITCH + (c << 3)) = *(const uint4*)(g_Gl + (size_t)(kq*64 + r)*DL + e0 + (c << 3));
        }
        __syncthreads();
        #pragma unroll
        for (int i = 0; i < 2; i++)
            #pragma unroll
            for (int j = 0; j < 8; j++)
                #pragma unroll
                for (int q = 0; q < 4; q++) acc2[i][j][q] = 0.f;
        #pragma unroll
        for (int ks = 0; ks < 4; ks++){
            uint32_t th[2][4], tl[2][4];
            #pragma unroll
            for (int mt = 0; mt < 2; mt++){
                int off = (wm*32 + mt*16 + lrow)*TPITCH + kq*64 + ks*16 + lcol;
                ldsm4(th[mt], t1h + off);
                ldsm4(tl[mt], t1l + off);
            }
            #pragma unroll
            for (int pp = 0; pp < 4; pp++){
                uint32_t bh[4], bl[4];
                int off = (ks*16 + lrow)*GPITCH + wn*64 + pp*16 + lcol;
                ldsm4t(bh, Ghs + off);
                ldsm4t(bl, Gls + off);
                #pragma unroll
                for (int mt = 0; mt < 2; mt++){
                    mma_bf16(acc2[mt][2*pp],   th[mt], bh);
                    mma_bf16(acc2[mt][2*pp],   th[mt], bl);
                    mma_bf16(acc2[mt][2*pp],   tl[mt], bh);
                    mma_bf16(acc2[mt][2*pp+1], th[mt], bh + 2);
                    mma_bf16(acc2[mt][2*pp+1], th[mt], bl + 2);
                    mma_bf16(acc2[mt][2*pp+1], tl[mt], bh + 2);
                }
            }
        }
        // epilogue: fp32 stores, coalesced float2
        #pragma unroll
        for (int mt = 0; mt < 2; mt++){
            int rr = row0 + wm*32 + mt*16 + (lane >> 2);
            int cb = kq*1024 + e0 + wn*64 + ((lane & 3) << 1);
            #pragma unroll
            for (int nt = 0; nt < 8; nt++){
                float2 v01 = make_float2(acc2[mt][nt][0], acc2[mt][nt][1]);
                float2 v23 = make_float2(acc2[mt][nt][2], acc2[mt][nt][3]);
                *(float2*)(out + (size_t)rr*DOUT + cb + nt*8)       = v01;
                *(float2*)(out + (size_t)(rr + 8)*DOUT + cb + nt*8) = v23;
            }
        }
        __syncthreads();
    }
}

// ------------------------- launch ------------------------------------------
extern "C" void kernel_launch(void* const* d_in, const int* in_sizes, int n_in,
                              void* d_out, int out_size){
    // positional default, then robust size-based matching (all sizes distinct)
    const float* x = (const float*)d_in[0];
    const float* W = (const float*)d_in[1];
    const float* A = (const float*)d_in[2];
    const float* B = (const float*)d_in[3];
    for (int i = 0; i < n_in; i++){
        switch (in_sizes[i]){
            case 16777216: x = (const float*)d_in[i]; break;   // [2,8192,1024]
            case 1769472:  W = (const float*)d_in[i]; break;   // [2304,768]
            case 196608:   A = (const float*)d_in[i]; break;   // [3,1024,64]
            case 147456:   B = (const float*)d_in[i]; break;   // [3,64,768]
            default: break;
        }
    }
    float* out = (float*)d_out;

    cudaFuncSetAttribute(qkv_main, cudaFuncAttributeMaxDynamicSharedMemorySize, SMEM_BYTES);

    p0_U    <<<dim3(3,24), 256>>>(B, W);
    p0_V    <<<dim3(3,4),  256>>>(B);
    p0_Vred <<<48,         256>>>();
    p0_G    <<<dim3(3,16), 256>>>(A);
    p0_splitA<<<768,       256>>>(A);
    p0_splitG<<<768,       256>>>();
    qkv_main<<<128, 256, SMEM_BYTES>>>(x, out);
}

// round 4
// speedup vs baseline: 1.4373x; 1.4373x over previous
#include <cuda_runtime.h>
#include <cuda_bf16.h>
#include <cstdint>

// ---------------------------------------------------------------------------
// QKVProjectedLinear, single-launch fused kernel (mma.sync/HMMA path):
//   G_k = (B_k Ws_k^T B_k^T) A_k^T  [64,1024]   (phase-0 CTAs 128..147)
//   t1  = x @ A_all                 [16384,192] (stage 1, bf16 hi/lo x3)
//   out_k = t1_k @ G_k                          (stage 2)
// ---------------------------------------------------------------------------

#define K3 3
#define DL 1024
#define DS 768
#define RK 64
#define NJ 192
#define DOUT 3072
#define NWORK 128
#define NP0 20

// ------------------------- device scratch ----------------------------------
__device__ __align__(16) float g_U[K3*RK*DS];            // B @ Ws^T   [3,64,768]
__device__ __align__(16) float g_Vp[K3*4*RK*RK];         // partial V  [3,4,64,64]
__device__ __align__(16) __nv_bfloat16 g_Ah[DL*NJ];      // A_all hi [1024,192]
__device__ __align__(16) __nv_bfloat16 g_Al[DL*NJ];
__device__ __align__(16) __nv_bfloat16 g_Gh[K3*RK*DL];   // G hi [3,64,1024]
__device__ __align__(16) __nv_bfloat16 g_Gl[K3*RK*DL];
__device__ int c_A, c_U, c_V, c_G;                        // monotonic flags

__device__ __forceinline__ void splitf(float v, __nv_bfloat16& h, __nv_bfloat16& l){
    h = __float2bfloat16(v);
    l = __float2bfloat16(v - __bfloat162float(h));
}
__device__ __forceinline__ uint32_t pack2(__nv_bfloat16 a, __nv_bfloat16 b){
    __nv_bfloat162 t; t.x = a; t.y = b;
    return *reinterpret_cast<uint32_t*>(&t);
}

// ------------------------- sync helpers ------------------------------------
__device__ __forceinline__ void flag_inc(int* f){
    __syncthreads();
    __threadfence();
    if (threadIdx.x == 0)
        asm volatile("red.release.gpu.global.add.s32 [%0], 1;" :: "l"(f) : "memory");
}
__device__ __forceinline__ void flag_wait(int* f, int thr){
    if (threadIdx.x == 0){
        int v;
        do {
            asm volatile("ld.acquire.gpu.global.s32 %0, [%1];" : "=r"(v) : "l"(f));
            if (v < thr) __nanosleep(128);
        } while (v < thr);
    }
    __syncthreads();
}

// ------------------------- cp.async helpers --------------------------------
__device__ __forceinline__ uint32_t smem_u32(const void* p){
    uint32_t a;
    asm("{ .reg .u64 t; cvta.to.shared.u64 t, %1; cvt.u32.u64 %0, t; }" : "=r"(a) : "l"(p));
    return a;
}
__device__ __forceinline__ void cpa16(uint32_t dst, const void* src){
    asm volatile("cp.async.cg.shared.global [%0], [%1], 16;" :: "r"(dst), "l"(src) : "memory");
}
#define CPA_COMMIT() asm volatile("cp.async.commit_group;" ::: "memory")
#define CPA_WAIT(n)  asm volatile("cp.async.wait_group %0;" :: "n"(n) : "memory")

// ------------------------- mma helpers --------------------------------------
__device__ __forceinline__ void ldsm4(uint32_t* r, const void* p){
    uint32_t a = smem_u32(p);
    asm volatile("ldmatrix.sync.aligned.m8n8.x4.shared.b16 {%0,%1,%2,%3}, [%4];"
        : "=r"(r[0]), "=r"(r[1]), "=r"(r[2]), "=r"(r[3]) : "r"(a));
}
__device__ __forceinline__ void ldsm4t(uint32_t* r, const void* p){
    uint32_t a = smem_u32(p);
    asm volatile("ldmatrix.sync.aligned.m8n8.x4.trans.shared.b16 {%0,%1,%2,%3}, [%4];"
        : "=r"(r[0]), "=r"(r[1]), "=r"(r[2]), "=r"(r[3]) : "r"(a));
}
__device__ __forceinline__ void mma_bf16(float* c, const uint32_t* a, const uint32_t* b){
    asm volatile("mma.sync.aligned.m16n8k16.row.col.f32.bf16.bf16.f32 "
        "{%0,%1,%2,%3}, {%4,%5,%6,%7}, {%8,%9}, {%0,%1,%2,%3};"
        : "+f"(c[0]), "+f"(c[1]), "+f"(c[2]), "+f"(c[3])
        : "r"(a[0]), "r"(a[1]), "r"(a[2]), "r"(a[3]), "r"(b[0]), "r"(b[1]));
}

// ------------------------- phase-0 jobs (use dynamic smem) ------------------
// U[k,r,s] = sum_t B[k,r,t] * W[(k*768+s), t]
__device__ void p0U_job(int k, int s0, char* smem,
                        const float* __restrict__ B, const float* __restrict__ W){
    float* Bt = (float*)smem;          // [64][65]
    float* Wt = Bt + 64*65;            // [32][65]
    int tid = threadIdx.x;
    float acc[2][4] = {};
    int r0 = (tid & 31)*2, sq = (tid >> 5)*4;
    for (int t0 = 0; t0 < DS; t0 += 64){
        __syncthreads();
        #pragma unroll
        for (int i = 0; i < 16; i++){
            int idx = tid + (i<<8); int r = idx>>6, t = idx&63;
            Bt[r*65 + t] = B[(k*64 + r)*DS + t0 + t];
        }
        #pragma unroll
        for (int i = 0; i < 8; i++){
            int idx = tid + (i<<8); int s = idx>>6, t = idx&63;
            Wt[s*65 + t] = W[(size_t)(k*DS + s0 + s)*DS + t0 + t];
        }
        __syncthreads();
        #pragma unroll 8
        for (int t = 0; t < 64; t++){
            float a0 = Bt[r0*65 + t], a1 = Bt[(r0+1)*65 + t];
            #pragma unroll
            for (int j = 0; j < 4; j++){
                float b = Wt[(sq+j)*65 + t];
                acc[0][j] += a0*b;
                acc[1][j] += a1*b;
            }
        }
    }
    #pragma unroll
    for (int i = 0; i < 2; i++)
        #pragma unroll
        for (int j = 0; j < 4; j++)
            g_U[(k*64 + r0 + i)*DS + s0 + sq + j] = acc[i][j];
}

// Vp[k,sc,r,q] = sum_{s in chunk sc} U[k,r,s] * B[k,q,s]
__device__ void p0V_job(int k, int sc, char* smem, const float* __restrict__ B){
    float* Us = (float*)smem;          // [64][65]
    float* Bs = Us + 64*65;
    int tid = threadIdx.x;
    float acc[4][4] = {};
    int r0 = (tid & 15)*4, q0 = (tid >> 4)*4;
    for (int si = 0; si < 3; si++){
        int s0 = sc*192 + si*64;
        __syncthreads();
        #pragma unroll
        for (int i = 0; i < 16; i++){
            int idx = tid + (i<<8); int r = idx>>6, s = idx&63;
            Us[r*65 + s] = g_U[(k*64 + r)*DS + s0 + s];
            Bs[r*65 + s] = B[(k*64 + r)*DS + s0 + s];
        }
        __syncthreads();
        #pragma unroll 4
        for (int s = 0; s < 64; s++){
            float a[4], b[4];
            #pragma unroll
            for (int i = 0; i < 4; i++){ a[i] = Us[(r0+i)*65 + s]; b[i] = Bs[(q0+i)*65 + s]; }
            #pragma unroll
            for (int i = 0; i < 4; i++)
                #pragma unroll
                for (int j = 0; j < 4; j++) acc[i][j] += a[i]*b[j];
        }
    }
    #pragma unroll
    for (int i = 0; i < 4; i++)
        #pragma unroll
        for (int j = 0; j < 4; j++)
            g_Vp[((k*4 + sc)*64 + r0 + i)*64 + q0 + j] = acc[i][j];
}

// G[k,r,e] = sum_q V[k,r,q] * A[k,e,q]; writes split bf16 directly
__device__ void p0G_job(int k, int e0, char* smem, const float* __restrict__ A){
    float* Vs = (float*)smem;          // [64][68]
    float* As = Vs + 64*68;
    int tid = threadIdx.x;
    __syncthreads();
    #pragma unroll
    for (int i = 0; i < 16; i++){
        int idx = tid + (i<<8); int a = idx>>6, b = idx&63;
        float v = 0.f;
        #pragma unroll
        for (int sc = 0; sc < 4; sc++) v += g_Vp[((k*4 + sc)*64 + a)*64 + b];
        Vs[a*68 + b] = v;
        As[a*68 + b] = A[(size_t)(k*DL + e0 + a)*RK + b];
    }
    __syncthreads();
    int r0 = (tid & 15)*4, ee = (tid >> 4)*4;
    float acc[4][4] = {};
    #pragma unroll 4
    for (int q = 0; q < 64; q++){
        float a[4], b[4];
        #pragma unroll
        for (int i = 0; i < 4; i++){ a[i] = Vs[(r0+i)*68 + q]; b[i] = As[(ee+i)*68 + q]; }
        #pragma unroll
        for (int i = 0; i < 4; i++)
            #pragma unroll
            for (int j = 0; j < 4; j++) acc[i][j] += a[i]*b[j];
    }
    #pragma unroll
    for (int i = 0; i < 4; i++)
        #pragma unroll
        for (int j = 0; j < 4; j++){
            __nv_bfloat16 h, l;
            splitf(acc[i][j], h, l);
            size_t dst = (size_t)(k*64 + r0 + i)*DL + e0 + ee + j;
            g_Gh[dst] = h;
            g_Gl[dst] = l;
        }
}

__device__ void phase0(char* smem, const float* __restrict__ W,
                       const float* __restrict__ A, const float* __restrict__ B){
    const int p = blockIdx.x - NWORK;
    const int tid = threadIdx.x;

    // --- splitA: A[k,d,r] -> g_Ah/g_Al [d][k*64+r]
    for (int idx = p*256 + tid; idx < K3*DL*RK; idx += NP0*256){
        int k = idx/(DL*RK); int rem = idx%(DL*RK); int d = rem/RK; int r = rem%RK;
        __nv_bfloat16 h, l;
        splitf(A[idx], h, l);
        g_Ah[d*NJ + k*RK + r] = h;
        g_Al[d*NJ + k*RK + r] = l;
    }
    flag_inc(&c_A);

    // --- U: 72 jobs
    for (int j = p; j < 72; j += NP0)
        p0U_job(j/24, (j%24)*32, smem, B, W);
    flag_inc(&c_U);
    flag_wait(&c_U, NP0);

    // --- V: 12 jobs
    if (p < 12){
        p0V_job(p/4, p%4, smem, B);
        flag_inc(&c_V);
    }
    flag_wait(&c_V, 12);

    // --- G: 48 jobs (writes split g_Gh/g_Gl directly)
    for (int j = p; j < 48; j += NP0)
        p0G_job(j/16, (j%16)*64, smem, A);
    flag_inc(&c_G);
}

// ------------------------- worker smem layout -------------------------------
// stage1: xh [128][72]bf16 @0 (18432), xl @18432 (end 36864)
//         A bufs [b][hl] [64][200]bf16 @36864 + b*51200 + hl*25600 (end 139264)
// stage2: t1h [128][200]bf16 @0, t1l @51200 (end 102400)  (aliases stage1 x/A)
//         G bufs [b][hl] [64][136]bf16 @102400 + b*34816 + hl*17408 (end 172032)
#define XH_OFF 0
#define XL_OFF 18432
#define AOFF(b,hl)  (36864 + (b)*51200 + (hl)*25600)
#define T1H_OFF 0
#define T1L_OFF 51200
#define GOFF(b,hl)  (102400 + (b)*34816 + (hl)*17408)
#define SMEM_BYTES  172032
#define XPITCH 72
#define APITCH 200
#define TPITCH 200
#define GPITCH 136

__device__ __forceinline__ void issueA(uint32_t sbase, char* smem, int ci, int b){
    const char* sh = (const char*)g_Ah + (size_t)ci*24576;
    const char* sl = (const char*)g_Al + (size_t)ci*24576;
    uint32_t dh = sbase + AOFF(b,0);
    uint32_t dl = sbase + AOFF(b,1);
    int tid = threadIdx.x;
    #pragma unroll
    for (int i = 0; i < 6; i++){
        int j = tid + (i << 8);
        int r = j / 24, c = j % 24;
        cpa16(dh + r*400 + c*16, sh + j*16);
        cpa16(dl + r*400 + c*16, sl + j*16);
    }
}
__device__ __forceinline__ void issueG(uint32_t sbase, int kq, int nt, int b){
    int e0 = nt << 7;
    const char* sh = (const char*)g_Gh;
    const char* sl = (const char*)g_Gl;
    uint32_t dh = sbase + GOFF(b,0);
    uint32_t dl = sbase + GOFF(b,1);
    int tid = threadIdx.x;
    #pragma unroll
    for (int i = 0; i < 4; i++){
        int j = tid + (i << 8);
        int r = j >> 4, c = j & 15;
        size_t so = ((size_t)(kq*64 + r)*DL + e0)*2 + c*16;
        cpa16(dh + r*272 + c*16, sh + so);
        cpa16(dl + r*272 + c*16, sl + so);
    }
}

__global__ __launch_bounds__(256, 1)
void qkv_main(const float* __restrict__ x, const float* __restrict__ W,
              const float* __restrict__ A, const float* __restrict__ B,
              float* __restrict__ out){
    extern __shared__ char smem[];

    if (blockIdx.x >= NWORK){
        phase0(smem, W, A, B);
        return;
    }

    __nv_bfloat16* xh  = (__nv_bfloat16*)(smem + XH_OFF);
    __nv_bfloat16* xl  = (__nv_bfloat16*)(smem + XL_OFF);
    __nv_bfloat16* t1h = (__nv_bfloat16*)(smem + T1H_OFF);
    __nv_bfloat16* t1l = (__nv_bfloat16*)(smem + T1L_OFF);

    const int tid  = threadIdx.x;
    const int warp = tid >> 5, lane = tid & 31;
    const int wm = warp >> 1, wn = warp & 1;
    const int row0 = blockIdx.x * 128;
    const int lrow = lane & 15;
    const int lcol = (lane >> 4) << 3;
    const uint32_t sbase = smem_u32(smem);

    // ===== stage 1: t1[128,192] = x[128,1024] @ A_all ======================
    float acc[2][12][4];
    #pragma unroll
    for (int i = 0; i < 2; i++)
        #pragma unroll
        for (int j = 0; j < 12; j++)
            #pragma unroll
            for (int q = 0; q < 4; q++) acc[i][j][q] = 0.f;

    // prefetch x chunk 0 into regs
    float4 xr[8];
    #pragma unroll
    for (int i = 0; i < 8; i++){
        int idx = tid + (i << 8);
        int r = idx >> 4, c4 = idx & 15;
        xr[i] = *(const float4*)(x + (size_t)(row0 + r)*DL + (c4 << 2));
    }

    flag_wait(&c_A, NP0);
    issueA(sbase, smem, 0, 0);
    CPA_COMMIT();

    for (int ci = 0; ci < 16; ci++){
        const int b = ci & 1;
        // split+store current x regs into smem
        #pragma unroll
        for (int i = 0; i < 8; i++){
            int idx = tid + (i << 8);
            int r = idx >> 4, c4 = idx & 15;
            __nv_bfloat16 h0,h1,h2,h3,l0,l1,l2,l3;
            splitf(xr[i].x,h0,l0); splitf(xr[i].y,h1,l1);
            splitf(xr[i].z,h2,l2); splitf(xr[i].w,h3,l3);
            uint2 ph; ph.x = pack2(h0,h1); ph.y = pack2(h2,h3);
            uint2 pl; pl.x = pack2(l0,l1); pl.y = pack2(l2,l3);
            *(uint2*)(xh + r*XPITCH + (c4 << 2)) = ph;
            *(uint2*)(xl + r*XPITCH + (c4 << 2)) = pl;
        }
        if (ci < 15){
            // prefetch next x chunk
            int d0 = (ci + 1) << 6;
            #pragma unroll
            for (int i = 0; i < 8; i++){
                int idx = tid + (i << 8);
                int r = idx >> 4, c4 = idx & 15;
                xr[i] = *(const float4*)(x + (size_t)(row0 + r)*DL + d0 + (c4 << 2));
            }
            issueA(sbase, smem, ci + 1, (ci + 1) & 1);
            CPA_COMMIT();
            CPA_WAIT(1);
        } else {
            CPA_WAIT(0);
        }
        __syncthreads();

        __nv_bfloat16* Ahs = (__nv_bfloat16*)(smem + AOFF(b,0));
        __nv_bfloat16* Als = (__nv_bfloat16*)(smem + AOFF(b,1));
        #pragma unroll
        for (int ks = 0; ks < 4; ks++){
            uint32_t ah[2][4], al[2][4];
            #pragma unroll
            for (int mt = 0; mt < 2; mt++){
                int off = (wm*32 + mt*16 + lrow)*XPITCH + ks*16 + lcol;
                ldsm4(ah[mt], xh + off);
                ldsm4(al[mt], xl + off);
            }
            #pragma unroll
            for (int pp = 0; pp < 6; pp++){
                uint32_t bh[4], bl[4];
                int off = (ks*16 + lrow)*APITCH + wn*96 + pp*16 + lcol;
                ldsm4t(bh, Ahs + off);
                ldsm4t(bl, Als + off);
                #pragma unroll
                for (int mt = 0; mt < 2; mt++){
                    mma_bf16(acc[mt][2*pp],   ah[mt], bh);
                    mma_bf16(acc[mt][2*pp],   ah[mt], bl);
                    mma_bf16(acc[mt][2*pp],   al[mt], bh);
                    mma_bf16(acc[mt][2*pp+1], ah[mt], bh + 2);
                    mma_bf16(acc[mt][2*pp+1], ah[mt], bl + 2);
                    mma_bf16(acc[mt][2*pp+1], al[mt], bh + 2);
                }
            }
        }
        __syncthreads();
    }

    // spill t1 (split hi/lo) to smem
    #pragma unroll
    for (int mt = 0; mt < 2; mt++){
        int r0w = wm*32 + mt*16 + (lane >> 2);
        #pragma unroll
        for (int nt = 0; nt < 12; nt++){
            int c0 = wn*96 + nt*8 + ((lane & 3) << 1);
            __nv_bfloat16 h0,h1,l0,l1;
            splitf(acc[mt][nt][0], h0, l0); splitf(acc[mt][nt][1], h1, l1);
            *(uint32_t*)(t1h + r0w*TPITCH + c0) = pack2(h0,h1);
            *(uint32_t*)(t1l + r0w*TPITCH + c0) = pack2(l0,l1);
            splitf(acc[mt][nt][2], h0, l0); splitf(acc[mt][nt][3], h1, l1);
            *(uint32_t*)(t1h + (r0w+8)*TPITCH + c0) = pack2(h0,h1);
            *(uint32_t*)(t1l + (r0w+8)*TPITCH + c0) = pack2(l0,l1);
        }
    }
    __syncthreads();

    // ===== stage 2: out chunks [128][128] = t1_k @ G_k chunk ===============
    flag_wait(&c_G, NP0);
    issueG(sbase, 0, 0, 0);
    CPA_COMMIT();

    float acc2[2][8][4];
    for (int t = 0; t < 24; t++){
        const int b = t & 1;
        const int kq = t >> 3, nt = t & 7;
        if (t < 23){
            int tn = t + 1;
            issueG(sbase, tn >> 3, tn & 7, tn & 1);
            CPA_COMMIT();
            CPA_WAIT(1);
        } else {
            CPA_WAIT(0);
        }
        __syncthreads();

        #pragma unroll
        for (int i = 0; i < 2; i++)
            #pragma unroll
            for (int j = 0; j < 8; j++)
                #pragma unroll
                for (int q = 0; q < 4; q++) acc2[i][j][q] = 0.f;

        __nv_bfloat16* Ghs = (__nv_bfloat16*)(smem + GOFF(b,0));
        __nv_bfloat16* Gls = (__nv_bfloat16*)(smem + GOFF(b,1));
        #pragma unroll
        for (int ks = 0; ks < 4; ks++){
            uint32_t th[2][4], tl[2][4];
            #pragma unroll
            for (int mt = 0; mt < 2; mt++){
                int off = (wm*32 + mt*16 + lrow)*TPITCH + kq*64 + ks*16 + lcol;
                ldsm4(th[mt], t1h + off);
                ldsm4(tl[mt], t1l + off);
            }
            #pragma unroll
            for (int pp = 0; pp < 4; pp++){
                uint32_t bh[4], bl[4];
                int off = (ks*16 + lrow)*GPITCH + wn*64 + pp*16 + lcol;
                ldsm4t(bh, Ghs + off);
                ldsm4t(bl, Gls + off);
                #pragma unroll
                for (int mt = 0; mt < 2; mt++){
                    mma_bf16(acc2[mt][2*pp],   th[mt], bh);
                    mma_bf16(acc2[mt][2*pp],   th[mt], bl);
                    mma_bf16(acc2[mt][2*pp],   tl[mt], bh);
                    mma_bf16(acc2[mt][2*pp+1], th[mt], bh + 2);
                    mma_bf16(acc2[mt][2*pp+1], th[mt], bl + 2);
                    mma_bf16(acc2[mt][2*pp+1], tl[mt], bh + 2);
                }
            }
        }
        // epilogue: fp32 stores
        int e0 = nt << 7;
        #pragma unroll
        for (int mt = 0; mt < 2; mt++){
            int rr = row0 + wm*32 + mt*16 + (lane >> 2);
            int cb = kq*1024 + e0 + wn*64 + ((lane & 3) << 1);
            #pragma unroll
            for (int ntt = 0; ntt < 8; ntt++){
                float2 v01 = make_float2(acc2[mt][ntt][0], acc2[mt][ntt][1]);
                float2 v23 = make_float2(acc2[mt][ntt][2], acc2[mt][ntt][3]);
                *(float2*)(out + (size_t)rr*DOUT + cb + ntt*8)       = v01;
                *(float2*)(out + (size_t)(rr + 8)*DOUT + cb + ntt*8) = v23;
            }
        }
        __syncthreads();
    }
}

// ------------------------- launch ------------------------------------------
extern "C" void kernel_launch(void* const* d_in, const int* in_sizes, int n_in,
                              void* d_out, int out_size){
    const float* x = (const float*)d_in[0];
    const float* W = (const float*)d_in[1];
    const float* A = (const float*)d_in[2];
    const float* B = (const float*)d_in[3];
    for (int i = 0; i < n_in; i++){
        switch (in_sizes[i]){
            case 16777216: x = (const float*)d_in[i]; break;   // [2,8192,1024]
            case 1769472:  W = (const float*)d_in[i]; break;   // [2304,768]
            case 196608:   A = (const float*)d_in[i]; break;   // [3,1024,64]
            case 147456:   B = (const float*)d_in[i]; break;   // [3,64,768]
            default: break;
        }
    }
    float* out = (float*)d_out;

    cudaFuncSetAttribute(qkv_main, cudaFuncAttributeMaxDynamicSharedMemorySize, SMEM_BYTES);
    qkv_main<<<NWORK + NP0, 256, SMEM_BYTES>>>(x, W, A, B, out);
}